// round 1
// baseline (speedup 1.0000x reference)
#include <cuda_runtime.h>
#include <math.h>
#include <stdint.h>

// ---------------------------------------------------------------------------
// Problem constants
// ---------------------------------------------------------------------------
namespace {
constexpr int Bb   = 2;
constexpr int Hh   = 512;
constexpr int Ww   = 512;
constexpr int Np   = Hh * Ww;        // 262144 pixels per image
constexpr int Cc   = 48;
constexpr int C3   = 144;            // 3*Cc
constexpr int HID  = 127;            // int(48*2.66)
constexpr int HID2 = 254;
constexpr int NPART  = 512;          // split-K partitions for the gram matrix
constexpr int CHUNK  = Np / NPART;   // 512 pixels per partition
constexpr int GSLOTS = 48 * 48 + 96; // 2400: G + nq + nk
}

// ---------------------------------------------------------------------------
// Scratch (static device globals: no allocation anywhere)
// ---------------------------------------------------------------------------
__device__ float g_patch[(size_t)Bb * Cc * Np];
__device__ float g_qkv0 [(size_t)Bb * C3 * Np];   // qkv pre-depthwise
__device__ float g_qkv  [(size_t)Bb * C3 * Np];   // qkv post-depthwise
__device__ float g_first[(size_t)Bb * Cc * Np];
__device__ float g_hbuf [(size_t)Bb * HID2 * Np];
__device__ float g_gate [(size_t)Bb * HID * Np];
__device__ float g_part [(size_t)Bb * NPART * GSLOTS];
__device__ float g_gfin [Bb * GSLOTS];
__device__ float g_M    [Bb * 48 * 48];           // po_w @ attn, per batch

// ---------------------------------------------------------------------------
// K1: patch embed conv 3x3, 3 -> 48, SAME pad.  One block per (b, row).
// 128 threads, 4 pixels each; inputs register-cached, weights in smem
// (each weight LDS broadcast amortized over 4 pixels -> 4 FMA / LDS).
// ---------------------------------------------------------------------------
__global__ __launch_bounds__(128) void k_pe(const float* __restrict__ x,
                                            const float* __restrict__ pw,
                                            float* __restrict__ out) {
  __shared__ float ws[48 * 27];
  __shared__ float si[3][3][514];
  int b = blockIdx.x / Hh, y = blockIdx.x % Hh;
  int tid = threadIdx.x;
  for (int i = tid; i < 48 * 27; i += 128) ws[i] = pw[i];
  for (int i = tid; i < 3 * 3 * 512; i += 128) {
    int ch = i / 1536, r = (i / 512) % 3, xx = i % 512;
    int yy = y - 1 + r;
    float v = (yy >= 0 && yy < Hh)
                  ? x[((size_t)(b * 3 + ch) * Hh + yy) * Ww + xx]
                  : 0.f;
    si[ch][r][xx + 1] = v;
  }
  if (tid < 9) {
    int ch = tid / 3, r = tid % 3;
    si[ch][r][0] = 0.f;
    si[ch][r][513] = 0.f;
  }
  __syncthreads();

  int x0 = tid * 4;
  float rv[3][3][6];
#pragma unroll
  for (int ch = 0; ch < 3; ch++)
#pragma unroll
    for (int r = 0; r < 3; r++)
#pragma unroll
      for (int d = 0; d < 6; d++) rv[ch][r][d] = si[ch][r][x0 + d];

  float* op = out + (size_t)b * Cc * Np + (size_t)y * Ww + x0;
  for (int o = 0; o < 48; o++) {
    float a0 = 0.f, a1 = 0.f, a2 = 0.f, a3 = 0.f;
#pragma unroll
    for (int ch = 0; ch < 3; ch++)
#pragma unroll
      for (int r = 0; r < 3; r++)
#pragma unroll
        for (int dx = 0; dx < 3; dx++) {
          float w = ws[o * 27 + ch * 9 + r * 3 + dx];
          a0 = fmaf(rv[ch][r][dx + 0], w, a0);
          a1 = fmaf(rv[ch][r][dx + 1], w, a1);
          a2 = fmaf(rv[ch][r][dx + 2], w, a2);
          a3 = fmaf(rv[ch][r][dx + 3], w, a3);
        }
    *reinterpret_cast<float4*>(op + (size_t)o * Np) = make_float4(a0, a1, a2, a3);
  }
}

// ---------------------------------------------------------------------------
// Generic pixel-GEMM: out[b,o,n] = (RES? res[b,o,n]:0) + sum_c A[b,c,n]*W[o,c]
// where A is optionally channel-LayerNormed per pixel (K must be 48 then).
// Tile: BM=128 pixels x BN outputs, 8x8 per-thread register blocking.
// ---------------------------------------------------------------------------
template <int K, int BN, bool LN, bool RES, bool PBW>
__global__ __launch_bounds__(BN * 2) void k_gemm(
    const float* __restrict__ in, int in_cs, int in_co,
    const float* __restrict__ w,
    const float* __restrict__ nw, const float* __restrict__ nb,
    const float* __restrict__ res, int res_cs,
    float* __restrict__ out, int out_cs, int CO) {
  constexpr int BM = 128, NT = BN * 2, BNp = BN + 4;
  extern __shared__ float sm[];
  float* sA = sm;                  // K * BM
  float* sB = sm + K * BM;         // K * BNp
  float* mu = sB + K * BNp;        // BM
  float* rs = mu + BM;             // BM

  int tid = threadIdx.x;
  int pb = blockIdx.x;
  int b = pb / (Np / BM);
  int n0 = (pb % (Np / BM)) * BM;
  int o0 = blockIdx.y * BN;

  const float* ip = in + ((size_t)b * in_cs + in_co) * Np + n0;
  for (int i = tid; i < K * BM; i += NT) {
    int c = i / BM, j = i % BM;
    sA[i] = ip[(size_t)c * Np + j];
  }
  const float* wp = PBW ? (w + (size_t)b * CO * K) : w;
  for (int i = tid; i < K * BN; i += NT) {
    int oo = i / K, c = i % K;
    int o = o0 + oo;
    sB[c * BNp + oo] = (o < CO) ? wp[(size_t)o * K + c] : 0.f;
  }
  __syncthreads();

  if constexpr (LN) {
    for (int j = tid; j < BM; j += NT) {
      float s = 0.f;
#pragma unroll 8
      for (int c = 0; c < K; c++) s += sA[c * BM + j];
      float m = s / (float)K;
      float v = 0.f;
#pragma unroll 8
      for (int c = 0; c < K; c++) {
        float d = sA[c * BM + j] - m;
        v = fmaf(d, d, v);
      }
      mu[j] = m;
      rs[j] = rsqrtf(v / (float)K + 1e-5f);
    }
    __syncthreads();
    for (int i = tid; i < K * BM; i += NT) {
      int c = i / BM, j = i % BM;
      sA[i] = (sA[i] - mu[j]) * rs[j] * nw[c] + nb[c];
    }
    __syncthreads();
  }

  int tp = tid & 15;       // pixel tile 0..15
  int to = tid >> 4;       // output tile 0..(BN/8-1)
  float acc[8][8];
#pragma unroll
  for (int i = 0; i < 8; i++)
#pragma unroll
    for (int j = 0; j < 8; j++) acc[i][j] = 0.f;

  const float* aBase = sA + tp * 8;
  const float* bBase = sB + to * 8;
#pragma unroll 4
  for (int c = 0; c < K; c++) {
    float4 a0 = *reinterpret_cast<const float4*>(aBase + c * BM);
    float4 a1 = *reinterpret_cast<const float4*>(aBase + c * BM + 4);
    float4 b0 = *reinterpret_cast<const float4*>(bBase + c * BNp);
    float4 b1 = *reinterpret_cast<const float4*>(bBase + c * BNp + 4);
    float av[8] = {a0.x, a0.y, a0.z, a0.w, a1.x, a1.y, a1.z, a1.w};
    float bv[8] = {b0.x, b0.y, b0.z, b0.w, b1.x, b1.y, b1.z, b1.w};
#pragma unroll
    for (int ko = 0; ko < 8; ko++)
#pragma unroll
      for (int kp = 0; kp < 8; kp++)
        acc[ko][kp] = fmaf(av[kp], bv[ko], acc[ko][kp]);
  }

#pragma unroll
  for (int ko = 0; ko < 8; ko++) {
    int o = o0 + to * 8 + ko;
    if (o >= CO) break;
    float* op = out + ((size_t)b * out_cs + o) * Np + n0 + tp * 8;
    float4 r0 = make_float4(acc[ko][0], acc[ko][1], acc[ko][2], acc[ko][3]);
    float4 r1 = make_float4(acc[ko][4], acc[ko][5], acc[ko][6], acc[ko][7]);
    if constexpr (RES) {
      const float* rp = res + ((size_t)b * res_cs + o) * Np + n0 + tp * 8;
      float4 q0 = *reinterpret_cast<const float4*>(rp);
      float4 q1 = *reinterpret_cast<const float4*>(rp + 4);
      r0.x += q0.x; r0.y += q0.y; r0.z += q0.z; r0.w += q0.w;
      r1.x += q1.x; r1.y += q1.y; r1.z += q1.z; r1.w += q1.w;
    }
    *reinterpret_cast<float4*>(op) = r0;
    *reinterpret_cast<float4*>(op + 4) = r1;
  }
}

// ---------------------------------------------------------------------------
// Depthwise 3x3 conv (SAME), 4 pixels per thread.
// ---------------------------------------------------------------------------
__global__ __launch_bounds__(256) void k_dw(const float* __restrict__ in,
                                            const float* __restrict__ w9,
                                            float* __restrict__ out, int Cn) {
  int idx = blockIdx.x * 256 + threadIdx.x;
  int total = Bb * Cn * (Np / 4);
  if (idx >= total) return;
  int xq = idx % (Ww / 4);
  int t = idx / (Ww / 4);
  int y = t % Hh; t /= Hh;
  int c = t % Cn;
  int b = t / Cn;
  int x0 = xq * 4;

  float wv[9];
#pragma unroll
  for (int i = 0; i < 9; i++) wv[i] = w9[c * 9 + i];

  const float* base = in + ((size_t)b * Cn + c) * Np;
  float a[4] = {0.f, 0.f, 0.f, 0.f};
#pragma unroll
  for (int dy = 0; dy < 3; dy++) {
    int yy = y + dy - 1;
    if (yy < 0 || yy >= Hh) continue;
    const float* row = base + (size_t)yy * Ww;
    float v[6];
    v[0] = (x0 > 0) ? row[x0 - 1] : 0.f;
    float4 m = *reinterpret_cast<const float4*>(row + x0);
    v[1] = m.x; v[2] = m.y; v[3] = m.z; v[4] = m.w;
    v[5] = (x0 + 4 < Ww) ? row[x0 + 4] : 0.f;
#pragma unroll
    for (int dx = 0; dx < 3; dx++) {
      float wt = wv[dy * 3 + dx];
#pragma unroll
      for (int p = 0; p < 4; p++) a[p] = fmaf(v[dx + p], wt, a[p]);
    }
  }
  *reinterpret_cast<float4*>(out + ((size_t)b * Cn + c) * Np + (size_t)y * Ww + x0) =
      make_float4(a[0], a[1], a[2], a[3]);
}

// ---------------------------------------------------------------------------
// GDFN: depthwise 3x3 on channels c and c+127 of h, then gelu(d1)*d2.
// ---------------------------------------------------------------------------
__global__ __launch_bounds__(256) void k_dwgelu(const float* __restrict__ in,
                                                const float* __restrict__ w9,
                                                float* __restrict__ out) {
  int idx = blockIdx.x * 256 + threadIdx.x;
  int total = Bb * HID * (Np / 4);
  if (idx >= total) return;
  int xq = idx % (Ww / 4);
  int t = idx / (Ww / 4);
  int y = t % Hh; t /= Hh;
  int c = t % HID;
  int b = t / HID;
  int x0 = xq * 4;

  float w1[9], w2[9];
#pragma unroll
  for (int i = 0; i < 9; i++) {
    w1[i] = w9[c * 9 + i];
    w2[i] = w9[(c + HID) * 9 + i];
  }
  const float* b1 = in + ((size_t)b * HID2 + c) * Np;
  const float* b2 = in + ((size_t)b * HID2 + c + HID) * Np;
  float a1[4] = {0.f, 0.f, 0.f, 0.f};
  float a2[4] = {0.f, 0.f, 0.f, 0.f};
#pragma unroll
  for (int dy = 0; dy < 3; dy++) {
    int yy = y + dy - 1;
    if (yy < 0 || yy >= Hh) continue;
    const float* r1 = b1 + (size_t)yy * Ww;
    const float* r2 = b2 + (size_t)yy * Ww;
    float v1[6], v2[6];
    v1[0] = (x0 > 0) ? r1[x0 - 1] : 0.f;
    v2[0] = (x0 > 0) ? r2[x0 - 1] : 0.f;
    float4 m1 = *reinterpret_cast<const float4*>(r1 + x0);
    float4 m2 = *reinterpret_cast<const float4*>(r2 + x0);
    v1[1] = m1.x; v1[2] = m1.y; v1[3] = m1.z; v1[4] = m1.w;
    v2[1] = m2.x; v2[2] = m2.y; v2[3] = m2.z; v2[4] = m2.w;
    v1[5] = (x0 + 4 < Ww) ? r1[x0 + 4] : 0.f;
    v2[5] = (x0 + 4 < Ww) ? r2[x0 + 4] : 0.f;
#pragma unroll
    for (int dx = 0; dx < 3; dx++) {
      float wa = w1[dy * 3 + dx];
      float wb = w2[dy * 3 + dx];
#pragma unroll
      for (int p = 0; p < 4; p++) {
        a1[p] = fmaf(v1[dx + p], wa, a1[p]);
        a2[p] = fmaf(v2[dx + p], wb, a2[p]);
      }
    }
  }
  float g[4];
#pragma unroll
  for (int p = 0; p < 4; p++) {
    float u = a1[p];
    g[p] = 0.5f * u * (1.f + erff(u * 0.70710678118654752f)) * a2[p];
  }
  *reinterpret_cast<float4*>(out + ((size_t)b * HID + c) * Np + (size_t)y * Ww + x0) =
      make_float4(g[0], g[1], g[2], g[3]);
}

// ---------------------------------------------------------------------------
// Gram partials: per block, partial G[48][48] = Q K^T over a pixel chunk,
// plus partial sum-of-squares norms. Deterministic (fixed slots, no atomics).
// 96 threads: 8 c-tiles(6) x 12 d-tiles(4).
// ---------------------------------------------------------------------------
__global__ __launch_bounds__(96) void k_gram(const float* __restrict__ qkv,
                                             float* __restrict__ part) {
  __shared__ float sQ[48 * 33];
  __shared__ float sK[48 * 33];
  int blk = blockIdx.x;
  int b = blk / NPART, pc = blk % NPART;
  int n0 = pc * CHUNK;
  const float* q = qkv + (size_t)b * C3 * Np;
  const float* k = q + (size_t)48 * Np;
  int tid = threadIdx.x;
  int ct = tid / 12, dt = tid % 12;
  int c0 = ct * 6, d0 = dt * 4;

  float acc[6][4];
#pragma unroll
  for (int i = 0; i < 6; i++)
#pragma unroll
    for (int j = 0; j < 4; j++) acc[i][j] = 0.f;
  float nacc = 0.f;

  for (int t = 0; t < CHUNK / 32; t++) {
    int off = n0 + t * 32;
    __syncthreads();
    for (int i = tid; i < 1536; i += 96) {
      int c = i / 32, j = i % 32;
      sQ[c * 33 + j] = q[(size_t)c * Np + off + j];
      sK[c * 33 + j] = k[(size_t)c * Np + off + j];
    }
    __syncthreads();
#pragma unroll 4
    for (int j = 0; j < 32; j++) {
      float qa[6], kb[4];
#pragma unroll
      for (int i = 0; i < 6; i++) qa[i] = sQ[(c0 + i) * 33 + j];
#pragma unroll
      for (int i = 0; i < 4; i++) kb[i] = sK[(d0 + i) * 33 + j];
#pragma unroll
      for (int i = 0; i < 6; i++)
#pragma unroll
        for (int jj = 0; jj < 4; jj++)
          acc[i][jj] = fmaf(qa[i], kb[jj], acc[i][jj]);
    }
    {
      const float* s = (tid < 48) ? (sQ + tid * 33) : (sK + (tid - 48) * 33);
#pragma unroll 8
      for (int j = 0; j < 32; j++) {
        float v = s[j];
        nacc = fmaf(v, v, nacc);
      }
    }
  }
  float* pp = part + (size_t)blk * GSLOTS;
#pragma unroll
  for (int i = 0; i < 6; i++)
#pragma unroll
    for (int jj = 0; jj < 4; jj++) pp[(c0 + i) * 48 + d0 + jj] = acc[i][jj];
  pp[2304 + tid] = nacc;
}

// Stage-2 reduction of gram partials (deterministic fixed order).
__global__ void k_red(const float* __restrict__ part, float* __restrict__ gfin) {
  int s = blockIdx.x * blockDim.x + threadIdx.x;
  if (s >= Bb * GSLOTS) return;
  int b = s / GSLOTS, slot = s % GSLOTS;
  const float* p = part + (size_t)b * NPART * GSLOTS + slot;
  float a0 = 0.f, a1 = 0.f, a2 = 0.f, a3 = 0.f;
  for (int i = 0; i < NPART; i += 4) {
    a0 += p[(size_t)(i + 0) * GSLOTS];
    a1 += p[(size_t)(i + 1) * GSLOTS];
    a2 += p[(size_t)(i + 2) * GSLOTS];
    a3 += p[(size_t)(i + 3) * GSLOTS];
  }
  gfin[s] = (a0 + a1) + (a2 + a3);
}

// softmax(G * temp / (||q|| ||k||)) then M = po_w @ attn, per batch.
__global__ __launch_bounds__(256) void k_att(const float* __restrict__ gfin,
                                             const float* __restrict__ temp,
                                             const float* __restrict__ po,
                                             float* __restrict__ M) {
  __shared__ float sG[2304];
  __shared__ float sAt[2304];
  __shared__ float snq[48], snk[48];
  int b = blockIdx.x, tid = threadIdx.x;
  const float* g = gfin + (size_t)b * GSLOTS;
  for (int i = tid; i < 2304; i += 256) sG[i] = g[i];
  if (tid < 96) {
    float nv = sqrtf(fmaxf(g[2304 + tid], 0.f));
    nv = fmaxf(nv, 1e-12f);
    if (tid < 48) snq[tid] = nv;
    else snk[tid - 48] = nv;
  }
  __syncthreads();
  float tv = temp[0];
  for (int i = tid; i < 2304; i += 256) {
    int c = i / 48, d = i % 48;
    sG[i] = sG[i] * tv / (snq[c] * snk[d]);
  }
  __syncthreads();
  if (tid < 48) {
    float mx = -1e30f;
    for (int d = 0; d < 48; d++) mx = fmaxf(mx, sG[tid * 48 + d]);
    float s = 0.f;
    for (int d = 0; d < 48; d++) {
      float e = expf(sG[tid * 48 + d] - mx);
      sAt[tid * 48 + d] = e;
      s += e;
    }
    float inv = 1.f / s;
    for (int d = 0; d < 48; d++) sAt[tid * 48 + d] *= inv;
  }
  __syncthreads();
  for (int i = tid; i < 2304; i += 256) {
    int o = i / 48, d = i % 48;
    float a = 0.f;
#pragma unroll 8
    for (int c = 0; c < 48; c++) a = fmaf(po[o * 48 + c], sAt[c * 48 + d], a);
    M[(size_t)b * 2304 + i] = a;
  }
}

// ---------------------------------------------------------------------------
// Launch
// ---------------------------------------------------------------------------
extern "C" void kernel_launch(void* const* d_in, const int* in_sizes, int n_in,
                              void* d_out, int out_size) {
  (void)in_sizes; (void)n_in; (void)out_size;
  const float* x      = (const float*)d_in[0];
  const float* pe_w   = (const float*)d_in[1];
  const float* n1_w   = (const float*)d_in[2];
  const float* n1_b   = (const float*)d_in[3];
  const float* temp   = (const float*)d_in[4];
  const float* qkv_w  = (const float*)d_in[5];
  const float* qkv_dw = (const float*)d_in[6];
  const float* po_w   = (const float*)d_in[7];
  const float* n2_w   = (const float*)d_in[8];
  const float* n2_b   = (const float*)d_in[9];
  const float* pi_w   = (const float*)d_in[10];
  const float* ffn_dw = (const float*)d_in[11];
  const float* fo_w   = (const float*)d_in[12];
  float* out = (float*)d_out;

  float *patch, *qkv0, *qkv, *first, *hbuf, *gate, *part, *gfin, *M;
  cudaGetSymbolAddress((void**)&patch, g_patch);
  cudaGetSymbolAddress((void**)&qkv0,  g_qkv0);
  cudaGetSymbolAddress((void**)&qkv,   g_qkv);
  cudaGetSymbolAddress((void**)&first, g_first);
  cudaGetSymbolAddress((void**)&hbuf,  g_hbuf);
  cudaGetSymbolAddress((void**)&gate,  g_gate);
  cudaGetSymbolAddress((void**)&part,  g_part);
  cudaGetSymbolAddress((void**)&gfin,  g_gfin);
  cudaGetSymbolAddress((void**)&M,     g_M);

  constexpr int SM_48_48  = (48 * 128 + 48 * 52 + 256) * 4;    // 35.6 KB
  constexpr int SM_48_64  = (48 * 128 + 48 * 68 + 256) * 4;    // 38.7 KB
  constexpr int SM_127_48 = (127 * 128 + 127 * 52 + 256) * 4;  // 92.5 KB
  cudaFuncSetAttribute(k_gemm<127, 48, false, true, false>,
                       cudaFuncAttributeMaxDynamicSharedMemorySize, SM_127_48);

  int gpix = Bb * Np / 128;  // 4096 pixel-blocks

  // 1. patch embed
  k_pe<<<Bb * Hh, 128>>>(x, pe_w, patch);

  // 2. LN(patch) -> qkv 1x1 (48 -> 144)
  k_gemm<48, 48, true, false, false><<<dim3(gpix, 3), 96, SM_48_48>>>(
      patch, Cc, 0, qkv_w, n1_w, n1_b, nullptr, 0, qkv0, C3, C3);

  // 3. depthwise 3x3 on qkv
  k_dw<<<(Bb * C3 * (Np / 4) + 255) / 256, 256>>>(qkv0, qkv_dw, qkv, C3);

  // 4-5. gram partials -> reduce -> softmax + fold po_w into M
  k_gram<<<Bb * NPART, 96>>>(qkv, part);
  k_red<<<(Bb * GSLOTS + 255) / 256, 256>>>(part, gfin);
  k_att<<<Bb, 256>>>(gfin, temp, po_w, M);

  // 6. first = patch + M @ v   (K=48 GEMM, per-batch weights M)
  k_gemm<48, 48, false, true, true><<<dim3(gpix, 1), 96, SM_48_48>>>(
      qkv, C3, 96, M, nullptr, nullptr, patch, Cc, first, Cc, Cc);

  // 7. LN(first) -> pi 1x1 (48 -> 254)
  k_gemm<48, 64, true, false, false><<<dim3(gpix, 4), 128, SM_48_64>>>(
      first, Cc, 0, pi_w, n2_w, n2_b, nullptr, 0, hbuf, HID2, HID2);

  // 8. depthwise 3x3 + exact-gelu gating (254 -> 127)
  k_dwgelu<<<(Bb * HID * (Np / 4) + 255) / 256, 256>>>(hbuf, ffn_dw, gate);

  // 9. out = first + fo 1x1 (127 -> 48)
  k_gemm<127, 48, false, true, false><<<dim3(gpix, 1), 96, SM_127_48>>>(
      gate, HID, 0, fo_w, nullptr, nullptr, first, Cc, out, Cc, Cc);
}

// round 2
// speedup vs baseline: 1.0762x; 1.0762x over previous
#include <cuda_runtime.h>
#include <math.h>
#include <stdint.h>

// ---------------------------------------------------------------------------
// Problem constants
// ---------------------------------------------------------------------------
namespace {
constexpr int Bb   = 2;
constexpr int Hh   = 512;
constexpr int Ww   = 512;
constexpr int Np   = Hh * Ww;        // 262144 pixels per image
constexpr int Cc   = 48;
constexpr int C3   = 144;            // 3*Cc
constexpr int HID  = 127;            // int(48*2.66)
constexpr int HID2 = 254;
constexpr int NPART  = 1024;         // split-K partitions for the gram matrix
constexpr int CHUNK  = Np / NPART;   // 256 pixels per partition
constexpr int GSLOTS = 48 * 48 + 96; // 2400: G + nq + nk
}

// ---------------------------------------------------------------------------
// Scratch (static device globals: no allocation anywhere)
// ---------------------------------------------------------------------------
__device__ float g_patch[(size_t)Bb * Cc * Np];
__device__ float g_qkv0 [(size_t)Bb * C3 * Np];   // qkv pre-depthwise
__device__ float g_qkv  [(size_t)Bb * C3 * Np];   // qkv post-depthwise
__device__ float g_first[(size_t)Bb * Cc * Np];
__device__ float g_hbuf [(size_t)Bb * HID2 * Np];
__device__ float g_gate [(size_t)Bb * HID * Np];
__device__ float g_part [(size_t)Bb * NPART * GSLOTS];
__device__ float g_gfin [Bb * GSLOTS];
__device__ float g_M    [Bb * 48 * 48];           // po_w @ attn, per batch

// ---------------------------------------------------------------------------
// tf32 helpers
// ---------------------------------------------------------------------------
__device__ __forceinline__ float tf32_hi(float x) {
  return __uint_as_float(__float_as_uint(x) & 0xFFFFE000u);
}
__device__ __forceinline__ void mma_tf32(float c[4], uint32_t a0, uint32_t a1,
                                         uint32_t a2, uint32_t a3, uint32_t b0,
                                         uint32_t b1) {
  asm volatile(
      "mma.sync.aligned.m16n8k8.row.col.f32.tf32.tf32.f32 "
      "{%0,%1,%2,%3}, {%4,%5,%6,%7}, {%8,%9}, {%0,%1,%2,%3};"
      : "+f"(c[0]), "+f"(c[1]), "+f"(c[2]), "+f"(c[3])
      : "r"(a0), "r"(a1), "r"(a2), "r"(a3), "r"(b0), "r"(b1));
}

// ---------------------------------------------------------------------------
// K1: patch embed conv 3x3, 3 -> 48, SAME pad.  One block per (b, row).
// ---------------------------------------------------------------------------
__global__ __launch_bounds__(128) void k_pe(const float* __restrict__ x,
                                            const float* __restrict__ pw,
                                            float* __restrict__ out) {
  __shared__ float ws[48 * 27];
  __shared__ float si[3][3][514];
  int b = blockIdx.x / Hh, y = blockIdx.x % Hh;
  int tid = threadIdx.x;
  for (int i = tid; i < 48 * 27; i += 128) ws[i] = pw[i];
  for (int i = tid; i < 3 * 3 * 512; i += 128) {
    int ch = i / 1536, r = (i / 512) % 3, xx = i % 512;
    int yy = y - 1 + r;
    float v = (yy >= 0 && yy < Hh)
                  ? x[((size_t)(b * 3 + ch) * Hh + yy) * Ww + xx]
                  : 0.f;
    si[ch][r][xx + 1] = v;
  }
  if (tid < 9) {
    int ch = tid / 3, r = tid % 3;
    si[ch][r][0] = 0.f;
    si[ch][r][513] = 0.f;
  }
  __syncthreads();

  int x0 = tid * 4;
  float rv[3][3][6];
#pragma unroll
  for (int ch = 0; ch < 3; ch++)
#pragma unroll
    for (int r = 0; r < 3; r++)
#pragma unroll
      for (int d = 0; d < 6; d++) rv[ch][r][d] = si[ch][r][x0 + d];

  float* op = out + (size_t)b * Cc * Np + (size_t)y * Ww + x0;
  for (int o = 0; o < 48; o++) {
    float a0 = 0.f, a1 = 0.f, a2 = 0.f, a3 = 0.f;
#pragma unroll
    for (int ch = 0; ch < 3; ch++)
#pragma unroll
      for (int r = 0; r < 3; r++)
#pragma unroll
        for (int dx = 0; dx < 3; dx++) {
          float w = ws[o * 27 + ch * 9 + r * 3 + dx];
          a0 = fmaf(rv[ch][r][dx + 0], w, a0);
          a1 = fmaf(rv[ch][r][dx + 1], w, a1);
          a2 = fmaf(rv[ch][r][dx + 2], w, a2);
          a3 = fmaf(rv[ch][r][dx + 3], w, a3);
        }
    *reinterpret_cast<float4*>(op + (size_t)o * Np) = make_float4(a0, a1, a2, a3);
  }
}

// ---------------------------------------------------------------------------
// Tensor-core pixel GEMM (tf32 hi/lo 3-pass for fp32-grade accuracy).
// out[b,o,n] = (RES? res[b,o,n]:0) + sum_c W[o,c] * A'[b,c,n]
// A' optionally channel-LayerNormed (requires K == KC, single chunk).
// Block tile: BN outputs x 128 pixels.  Warp tile: 16 outputs x 64 pixels.
// grid = (CO_tiles, pixel_tiles) so co-scheduled blocks share the input tile
// in L2.
// ---------------------------------------------------------------------------
template <int K, int KC, int BN, bool LN, bool RES, bool PBW>
__global__ __launch_bounds__((BN / 16) * 64) void k_tgemm(
    const float* __restrict__ in, int in_cs, int in_co,
    const float* __restrict__ w,
    const float* __restrict__ nw, const float* __restrict__ nb,
    const float* __restrict__ res, int res_cs,
    float* __restrict__ out, int out_cs, int CO) {
  constexpr int MT = BN / 16;     // m-tiles / warps along outputs
  constexpr int NTH = MT * 64;    // threads
  constexpr int SBd = 132;        // B row stride (float2), conflict-free
  constexpr int SAd = BN + 4;     // A row stride (float2), conflict-free
  constexpr int KSTEPS = KC / 8;

  extern __shared__ float2 sm2[];
  float2* sB = sm2;                         // [KC][SBd]
  float2* sA = sm2 + KC * SBd;              // [KC][SAd]
  float* tail = (float*)(sA + KC * SAd);
  float* mu = tail;        // 128
  float* rs = tail + 128;  // 128
  float* snw = tail + 256; // K (<=48 used with LN)
  float* snb = tail + 304;

  int tid = threadIdx.x;
  int wid = tid / 32, lane = tid % 32;
  int warp_m = wid % MT, warp_n = wid / MT;
  int n0 = warp_n * 64;
  int o0 = blockIdx.x * BN;
  int pb = blockIdx.y;
  int b = pb / (Np / 128);
  int n0g = (pb % (Np / 128)) * 128;

  const float* ip = in + ((size_t)b * in_cs + in_co) * Np + n0g;
  const float* wp = PBW ? (w + (size_t)b * CO * K) : w;

  float acc[8][4];
#pragma unroll
  for (int j = 0; j < 8; j++)
#pragma unroll
    for (int i = 0; i < 4; i++) acc[j][i] = 0.f;

  for (int k0 = 0; k0 < K; k0 += KC) {
    // ---- stage A (weights) hi/lo ----
    for (int i = tid; i < KC * BN; i += NTH) {
      int k = i / BN, m = i % BN;
      int o = o0 + m, kk = k0 + k;
      float wv = (o < CO && kk < K) ? wp[(size_t)o * K + kk] : 0.f;
      float h = tf32_hi(wv);
      sA[k * SAd + m] = make_float2(h, wv - h);
    }
    // ---- stage B (pixels) ----
    if constexpr (LN) {
      for (int i = tid; i < KC * 128; i += NTH) {
        int k = i >> 7, j = i & 127;
        sB[k * SBd + j].x = ip[(size_t)k * Np + j];
      }
      for (int i = tid; i < K; i += NTH) {
        snw[i] = nw[i];
        snb[i] = nb[i];
      }
      __syncthreads();
      for (int j = tid; j < 128; j += NTH) {
        float s = 0.f;
#pragma unroll 8
        for (int k = 0; k < K; k++) s += sB[k * SBd + j].x;
        float m = s * (1.f / (float)K);
        float v = 0.f;
#pragma unroll 8
        for (int k = 0; k < K; k++) {
          float d = sB[k * SBd + j].x - m;
          v = fmaf(d, d, v);
        }
        mu[j] = m;
        rs[j] = rsqrtf(v * (1.f / (float)K) + 1e-5f);
      }
      __syncthreads();
      for (int i = tid; i < KC * 128; i += NTH) {
        int k = i >> 7, j = i & 127;
        float xv = sB[k * SBd + j].x;
        float yv = (xv - mu[j]) * rs[j] * snw[k] + snb[k];
        float h = tf32_hi(yv);
        sB[k * SBd + j] = make_float2(h, yv - h);
      }
    } else {
      for (int i = tid; i < KC * 128; i += NTH) {
        int k = i >> 7, j = i & 127;
        int kk = k0 + k;
        float xv = (kk < K) ? ip[(size_t)kk * Np + j] : 0.f;
        float h = tf32_hi(xv);
        sB[k * SBd + j] = make_float2(h, xv - h);
      }
    }
    __syncthreads();

    // ---- mma main loop ----
    int tg = lane & 3, gr = lane >> 2;
#pragma unroll
    for (int ks = 0; ks < KSTEPS; ks++) {
      int kr0 = ks * 8 + tg;
      float2 a0 = sA[kr0 * SAd + warp_m * 16 + gr];
      float2 a1 = sA[kr0 * SAd + warp_m * 16 + gr + 8];
      float2 a2 = sA[(kr0 + 4) * SAd + warp_m * 16 + gr];
      float2 a3 = sA[(kr0 + 4) * SAd + warp_m * 16 + gr + 8];
      uint32_t ah0 = __float_as_uint(a0.x), al0 = __float_as_uint(a0.y);
      uint32_t ah1 = __float_as_uint(a1.x), al1 = __float_as_uint(a1.y);
      uint32_t ah2 = __float_as_uint(a2.x), al2 = __float_as_uint(a2.y);
      uint32_t ah3 = __float_as_uint(a3.x), al3 = __float_as_uint(a3.y);
#pragma unroll
      for (int j = 0; j < 8; j++) {
        float2 b0 = sB[kr0 * SBd + n0 + j * 8 + gr];
        float2 b1 = sB[(kr0 + 4) * SBd + n0 + j * 8 + gr];
        uint32_t bh0 = __float_as_uint(b0.x), bl0 = __float_as_uint(b0.y);
        uint32_t bh1 = __float_as_uint(b1.x), bl1 = __float_as_uint(b1.y);
        mma_tf32(acc[j], ah0, ah1, ah2, ah3, bh0, bh1);  // hi*hi
        mma_tf32(acc[j], ah0, ah1, ah2, ah3, bl0, bl1);  // hi*lo
        mma_tf32(acc[j], al0, al1, al2, al3, bh0, bh1);  // lo*hi
      }
    }
    if (k0 + KC < K) __syncthreads();
  }

  // ---- epilogue ----
  int gr = lane >> 2, tg = lane & 3;
#pragma unroll
  for (int j = 0; j < 8; j++) {
    int nn = n0 + j * 8 + 2 * tg;
#pragma unroll
    for (int h = 0; h < 2; h++) {
      int o = o0 + warp_m * 16 + gr + h * 8;
      if (o < CO) {
        float2 r = make_float2(acc[j][h * 2], acc[j][h * 2 + 1]);
        float* optr = out + ((size_t)b * out_cs + o) * Np + n0g + nn;
        if constexpr (RES) {
          const float2 q = *reinterpret_cast<const float2*>(
              res + ((size_t)b * res_cs + o) * Np + n0g + nn);
          r.x += q.x;
          r.y += q.y;
        }
        *reinterpret_cast<float2*>(optr) = r;
      }
    }
  }
}

// ---------------------------------------------------------------------------
// Depthwise 3x3 conv (SAME), 4 pixels per thread.
// ---------------------------------------------------------------------------
__global__ __launch_bounds__(256) void k_dw(const float* __restrict__ in,
                                            const float* __restrict__ w9,
                                            float* __restrict__ out, int Cn) {
  int idx = blockIdx.x * 256 + threadIdx.x;
  int total = Bb * Cn * (Np / 4);
  if (idx >= total) return;
  int xq = idx % (Ww / 4);
  int t = idx / (Ww / 4);
  int y = t % Hh; t /= Hh;
  int c = t % Cn;
  int b = t / Cn;
  int x0 = xq * 4;

  float wv[9];
#pragma unroll
  for (int i = 0; i < 9; i++) wv[i] = w9[c * 9 + i];

  const float* base = in + ((size_t)b * Cn + c) * Np;
  float a[4] = {0.f, 0.f, 0.f, 0.f};
#pragma unroll
  for (int dy = 0; dy < 3; dy++) {
    int yy = y + dy - 1;
    if (yy < 0 || yy >= Hh) continue;
    const float* row = base + (size_t)yy * Ww;
    float v[6];
    v[0] = (x0 > 0) ? row[x0 - 1] : 0.f;
    float4 m = *reinterpret_cast<const float4*>(row + x0);
    v[1] = m.x; v[2] = m.y; v[3] = m.z; v[4] = m.w;
    v[5] = (x0 + 4 < Ww) ? row[x0 + 4] : 0.f;
#pragma unroll
    for (int dx = 0; dx < 3; dx++) {
      float wt = wv[dy * 3 + dx];
#pragma unroll
      for (int p = 0; p < 4; p++) a[p] = fmaf(v[dx + p], wt, a[p]);
    }
  }
  *reinterpret_cast<float4*>(out + ((size_t)b * Cn + c) * Np + (size_t)y * Ww + x0) =
      make_float4(a[0], a[1], a[2], a[3]);
}

// ---------------------------------------------------------------------------
// GDFN: depthwise 3x3 on channels c and c+127 of h, then gelu(d1)*d2.
// ---------------------------------------------------------------------------
__global__ __launch_bounds__(256) void k_dwgelu(const float* __restrict__ in,
                                                const float* __restrict__ w9,
                                                float* __restrict__ out) {
  int idx = blockIdx.x * 256 + threadIdx.x;
  int total = Bb * HID * (Np / 4);
  if (idx >= total) return;
  int xq = idx % (Ww / 4);
  int t = idx / (Ww / 4);
  int y = t % Hh; t /= Hh;
  int c = t % HID;
  int b = t / HID;
  int x0 = xq * 4;

  float w1[9], w2[9];
#pragma unroll
  for (int i = 0; i < 9; i++) {
    w1[i] = w9[c * 9 + i];
    w2[i] = w9[(c + HID) * 9 + i];
  }
  const float* b1 = in + ((size_t)b * HID2 + c) * Np;
  const float* b2 = in + ((size_t)b * HID2 + c + HID) * Np;
  float a1[4] = {0.f, 0.f, 0.f, 0.f};
  float a2[4] = {0.f, 0.f, 0.f, 0.f};
#pragma unroll
  for (int dy = 0; dy < 3; dy++) {
    int yy = y + dy - 1;
    if (yy < 0 || yy >= Hh) continue;
    const float* r1 = b1 + (size_t)yy * Ww;
    const float* r2 = b2 + (size_t)yy * Ww;
    float v1[6], v2[6];
    v1[0] = (x0 > 0) ? r1[x0 - 1] : 0.f;
    v2[0] = (x0 > 0) ? r2[x0 - 1] : 0.f;
    float4 m1 = *reinterpret_cast<const float4*>(r1 + x0);
    float4 m2 = *reinterpret_cast<const float4*>(r2 + x0);
    v1[1] = m1.x; v1[2] = m1.y; v1[3] = m1.z; v1[4] = m1.w;
    v2[1] = m2.x; v2[2] = m2.y; v2[3] = m2.z; v2[4] = m2.w;
    v1[5] = (x0 + 4 < Ww) ? r1[x0 + 4] : 0.f;
    v2[5] = (x0 + 4 < Ww) ? r2[x0 + 4] : 0.f;
#pragma unroll
    for (int dx = 0; dx < 3; dx++) {
      float wa = w1[dy * 3 + dx];
      float wb = w2[dy * 3 + dx];
#pragma unroll
      for (int p = 0; p < 4; p++) {
        a1[p] = fmaf(v1[dx + p], wa, a1[p]);
        a2[p] = fmaf(v2[dx + p], wb, a2[p]);
      }
    }
  }
  float g[4];
#pragma unroll
  for (int p = 0; p < 4; p++) {
    float u = a1[p];
    g[p] = 0.5f * u * (1.f + erff(u * 0.70710678118654752f)) * a2[p];
  }
  *reinterpret_cast<float4*>(out + ((size_t)b * HID + c) * Np + (size_t)y * Ww + x0) =
      make_float4(g[0], g[1], g[2], g[3]);
}

// ---------------------------------------------------------------------------
// Gram partials: per block, partial G[48][48] = Q K^T over a pixel chunk,
// plus partial sum-of-squares norms. Deterministic (fixed slots, no atomics).
// ---------------------------------------------------------------------------
__global__ __launch_bounds__(96) void k_gram(const float* __restrict__ qkv,
                                             float* __restrict__ part) {
  __shared__ float sQ[48 * 33];
  __shared__ float sK[48 * 33];
  int blk = blockIdx.x;
  int b = blk / NPART, pc = blk % NPART;
  int n0 = pc * CHUNK;
  const float* q = qkv + (size_t)b * C3 * Np;
  const float* k = q + (size_t)48 * Np;
  int tid = threadIdx.x;
  int ct = tid / 12, dt = tid % 12;
  int c0 = ct * 6, d0 = dt * 4;

  float acc[6][4];
#pragma unroll
  for (int i = 0; i < 6; i++)
#pragma unroll
    for (int j = 0; j < 4; j++) acc[i][j] = 0.f;
  float nacc = 0.f;

  for (int t = 0; t < CHUNK / 32; t++) {
    int off = n0 + t * 32;
    __syncthreads();
    for (int i = tid; i < 1536; i += 96) {
      int c = i / 32, j = i % 32;
      sQ[c * 33 + j] = q[(size_t)c * Np + off + j];
      sK[c * 33 + j] = k[(size_t)c * Np + off + j];
    }
    __syncthreads();
#pragma unroll 4
    for (int j = 0; j < 32; j++) {
      float qa[6], kb[4];
#pragma unroll
      for (int i = 0; i < 6; i++) qa[i] = sQ[(c0 + i) * 33 + j];
#pragma unroll
      for (int i = 0; i < 4; i++) kb[i] = sK[(d0 + i) * 33 + j];
#pragma unroll
      for (int i = 0; i < 6; i++)
#pragma unroll
        for (int jj = 0; jj < 4; jj++)
          acc[i][jj] = fmaf(qa[i], kb[jj], acc[i][jj]);
    }
    {
      const float* s = (tid < 48) ? (sQ + tid * 33) : (sK + (tid - 48) * 33);
#pragma unroll 8
      for (int j = 0; j < 32; j++) {
        float v = s[j];
        nacc = fmaf(v, v, nacc);
      }
    }
  }
  float* pp = part + (size_t)blk * GSLOTS;
#pragma unroll
  for (int i = 0; i < 6; i++)
#pragma unroll
    for (int jj = 0; jj < 4; jj++) pp[(c0 + i) * 48 + d0 + jj] = acc[i][jj];
  pp[2304 + tid] = nacc;
}

// Stage-2 reduction of gram partials (deterministic fixed order).
__global__ void k_red(const float* __restrict__ part, float* __restrict__ gfin) {
  int s = blockIdx.x * blockDim.x + threadIdx.x;
  if (s >= Bb * GSLOTS) return;
  int b = s / GSLOTS, slot = s % GSLOTS;
  const float* p = part + (size_t)b * NPART * GSLOTS + slot;
  float a0 = 0.f, a1 = 0.f, a2 = 0.f, a3 = 0.f;
  for (int i = 0; i < NPART; i += 4) {
    a0 += p[(size_t)(i + 0) * GSLOTS];
    a1 += p[(size_t)(i + 1) * GSLOTS];
    a2 += p[(size_t)(i + 2) * GSLOTS];
    a3 += p[(size_t)(i + 3) * GSLOTS];
  }
  gfin[s] = (a0 + a1) + (a2 + a3);
}

// softmax(G * temp / (||q|| ||k||)) then M = po_w @ attn, per batch.
__global__ __launch_bounds__(256) void k_att(const float* __restrict__ gfin,
                                             const float* __restrict__ temp,
                                             const float* __restrict__ po,
                                             float* __restrict__ M) {
  __shared__ float sG[2304];
  __shared__ float sAt[2304];
  __shared__ float snq[48], snk[48];
  int b = blockIdx.x, tid = threadIdx.x;
  const float* g = gfin + (size_t)b * GSLOTS;
  for (int i = tid; i < 2304; i += 256) sG[i] = g[i];
  if (tid < 96) {
    float nv = sqrtf(fmaxf(g[2304 + tid], 0.f));
    nv = fmaxf(nv, 1e-12f);
    if (tid < 48) snq[tid] = nv;
    else snk[tid - 48] = nv;
  }
  __syncthreads();
  float tv = temp[0];
  for (int i = tid; i < 2304; i += 256) {
    int c = i / 48, d = i % 48;
    sG[i] = sG[i] * tv / (snq[c] * snk[d]);
  }
  __syncthreads();
  if (tid < 48) {
    float mx = -1e30f;
    for (int d = 0; d < 48; d++) mx = fmaxf(mx, sG[tid * 48 + d]);
    float s = 0.f;
    for (int d = 0; d < 48; d++) {
      float e = expf(sG[tid * 48 + d] - mx);
      sAt[tid * 48 + d] = e;
      s += e;
    }
    float inv = 1.f / s;
    for (int d = 0; d < 48; d++) sAt[tid * 48 + d] *= inv;
  }
  __syncthreads();
  for (int i = tid; i < 2304; i += 256) {
    int o = i / 48, d = i % 48;
    float a = 0.f;
#pragma unroll 8
    for (int c = 0; c < 48; c++) a = fmaf(po[o * 48 + c], sAt[c * 48 + d], a);
    M[(size_t)b * 2304 + i] = a;
  }
}

// ---------------------------------------------------------------------------
// Launch
// ---------------------------------------------------------------------------
extern "C" void kernel_launch(void* const* d_in, const int* in_sizes, int n_in,
                              void* d_out, int out_size) {
  (void)in_sizes; (void)n_in; (void)out_size;
  const float* x      = (const float*)d_in[0];
  const float* pe_w   = (const float*)d_in[1];
  const float* n1_w   = (const float*)d_in[2];
  const float* n1_b   = (const float*)d_in[3];
  const float* temp   = (const float*)d_in[4];
  const float* qkv_w  = (const float*)d_in[5];
  const float* qkv_dw = (const float*)d_in[6];
  const float* po_w   = (const float*)d_in[7];
  const float* n2_w   = (const float*)d_in[8];
  const float* n2_b   = (const float*)d_in[9];
  const float* pi_w   = (const float*)d_in[10];
  const float* ffn_dw = (const float*)d_in[11];
  const float* fo_w   = (const float*)d_in[12];
  float* out = (float*)d_out;

  float *patch, *qkv0, *qkv, *first, *hbuf, *gate, *part, *gfin, *M;
  cudaGetSymbolAddress((void**)&patch, g_patch);
  cudaGetSymbolAddress((void**)&qkv0,  g_qkv0);
  cudaGetSymbolAddress((void**)&qkv,   g_qkv);
  cudaGetSymbolAddress((void**)&first, g_first);
  cudaGetSymbolAddress((void**)&hbuf,  g_hbuf);
  cudaGetSymbolAddress((void**)&gate,  g_gate);
  cudaGetSymbolAddress((void**)&part,  g_part);
  cudaGetSymbolAddress((void**)&gfin,  g_gfin);
  cudaGetSymbolAddress((void**)&M,     g_M);

  // smem sizes (bytes): sB[KC][132]f2 + sA[KC][BN+4]f2 + 308 floats tail
  constexpr int SM_QKV = (48 * 132 + 48 * 52) * 8 + 1408;   // ~72.1 KB
  constexpr int SM_PI  = (48 * 132 + 48 * 68) * 8 + 1408;   // ~78.2 KB
  constexpr int SM_FO  = (64 * 132 + 64 * 52) * 8 + 1408;   // ~95.6 KB

  cudaFuncSetAttribute(k_tgemm<48, 48, 48, true, false, false>,
                       cudaFuncAttributeMaxDynamicSharedMemorySize, SM_QKV);
  cudaFuncSetAttribute(k_tgemm<48, 48, 48, false, true, true>,
                       cudaFuncAttributeMaxDynamicSharedMemorySize, SM_QKV);
  cudaFuncSetAttribute(k_tgemm<48, 48, 64, true, false, false>,
                       cudaFuncAttributeMaxDynamicSharedMemorySize, SM_PI);
  cudaFuncSetAttribute(k_tgemm<127, 64, 48, false, true, false>,
                       cudaFuncAttributeMaxDynamicSharedMemorySize, SM_FO);

  int gpix = Bb * Np / 128;  // 4096 pixel-blocks

  // 1. patch embed
  k_pe<<<Bb * Hh, 128>>>(x, pe_w, patch);

  // 2. LN(patch) -> qkv 1x1 (48 -> 144)
  k_tgemm<48, 48, 48, true, false, false><<<dim3(3, gpix), 192, SM_QKV>>>(
      patch, Cc, 0, qkv_w, n1_w, n1_b, nullptr, 0, qkv0, C3, C3);

  // 3. depthwise 3x3 on qkv
  k_dw<<<(Bb * C3 * (Np / 4) + 255) / 256, 256>>>(qkv0, qkv_dw, qkv, C3);

  // 4-5. gram partials -> reduce -> softmax + fold po_w into M
  k_gram<<<Bb * NPART, 96>>>(qkv, part);
  k_red<<<(Bb * GSLOTS + 255) / 256, 256>>>(part, gfin);
  k_att<<<Bb, 256>>>(gfin, temp, po_w, M);

  // 6. first = patch + M @ v   (K=48 GEMM, per-batch weights M)
  k_tgemm<48, 48, 48, false, true, true><<<dim3(1, gpix), 192, SM_QKV>>>(
      qkv, C3, 96, M, nullptr, nullptr, patch, Cc, first, Cc, Cc);

  // 7. LN(first) -> pi 1x1 (48 -> 254)
  k_tgemm<48, 48, 64, true, false, false><<<dim3(4, gpix), 256, SM_PI>>>(
      first, Cc, 0, pi_w, n2_w, n2_b, nullptr, 0, hbuf, HID2, HID2);

  // 8. depthwise 3x3 + exact-gelu gating (254 -> 127)
  k_dwgelu<<<(Bb * HID * (Np / 4) + 255) / 256, 256>>>(hbuf, ffn_dw, gate);

  // 9. out = first + fo 1x1 (127 -> 48)
  k_tgemm<127, 64, 48, false, true, false><<<dim3(1, gpix), 192, SM_FO>>>(
      gate, HID, 0, fo_w, nullptr, nullptr, first, Cc, out, Cc, Cc);
}